// round 14
// baseline (speedup 1.0000x reference)
#include <cuda_runtime.h>
#include <cuda_bf16.h>
#include <cstdint>
typedef unsigned long long ull;

#define BB 256
#define DD 1024
#define NSLOT 200000
#define KK 64
#define NCHUNK 148
#define CHUNK ((NSLOT+NCHUNK-1)/NCHUNK)  // 1352
#define TN 64

// dynamic smem offsets
#define QH_OFF 0u                 // 256 x 144B
#define QL_OFF 36864u
#define KH_OFF 73728u             // 2 bufs x 64 x 144B
#define KL_OFF 92160u
#define SF_OFF 110592u            // 2 bufs x 64 x 256B fp32
#define PP_OFF 143360u            // 2 bufs x 256B prio
#define PS_OFF 143872u            // 256 x 66 fp32
#define SMEM_SZ 211456
#define PSTR 66

__device__ __align__(16) unsigned short g_qh[BB*KK];
__device__ __align__(16) unsigned short g_ql[BB*KK];
__device__ __align__(16) unsigned short g_kh[(size_t)NSLOT*KK];
__device__ __align__(16) unsigned short g_kl[(size_t)NSLOT*KK];
__device__ __align__(16) float g_accpart[NCHUNK*BB*KK];
__device__ __align__(16) float g_denpart[NCHUNK*BB];
__device__ __align__(16) float g_ret[BB*KK];

__device__ __forceinline__ void cpasync16(unsigned d, const void* s, int sz){
    asm volatile("cp.async.cg.shared.global [%0], [%1], 16, %2;"::"r"(d),"l"(s),"r"(sz));
}
__device__ __forceinline__ void cpcommit(){ asm volatile("cp.async.commit_group;"); }
template<int N> __device__ __forceinline__ void cpwait(){
    asm volatile("cp.async.wait_group %0;"::"n"(N));
}
__device__ __forceinline__ unsigned lds32(unsigned a){
    unsigned v; asm volatile("ld.shared.b32 %0, [%1];":"=r"(v):"r"(a)); return v;
}
__device__ __forceinline__ void mma4(float* c, const unsigned* a, unsigned b0, unsigned b1){
    asm volatile("mma.sync.aligned.m16n8k16.row.col.f32.bf16.bf16.f32 "
                 "{%0,%1,%2,%3}, {%4,%5,%6,%7}, {%8,%9}, {%0,%1,%2,%3};"
                 :"+f"(c[0]),"+f"(c[1]),"+f"(c[2]),"+f"(c[3])
                 :"r"(a[0]),"r"(a[1]),"r"(a[2]),"r"(a[3]),"r"(b0),"r"(b1));
}
__device__ __forceinline__ ull ffma2(ull a, ull b, ull c){
    ull d; asm("fma.rn.f32x2 %0, %1, %2, %3;":"=l"(d):"l"(a),"l"(b),"l"(c)); return d;
}
__device__ __forceinline__ void lds2(ull& a, ull& b, unsigned ad){
    asm volatile("ld.shared.v2.b64 {%0, %1}, [%2];":"=l"(a),"=l"(b):"r"(ad));
}

// -------- kernel 1: cue projection + Q hi/lo split
__global__ __launch_bounds__(256)
void k_prep(const float* __restrict__ cue, const float* __restrict__ wcue){
    int b = blockIdx.x*4 + (threadIdx.x>>6);
    int k = threadIdx.x & 63;
    const float4* cr=(const float4*)(cue+(size_t)b*DD);
    const float4* wr=(const float4*)(wcue+(size_t)k*DD);
    float a0=0.f,a1=0.f,a2=0.f,a3=0.f;
#pragma unroll 8
    for(int j=0;j<DD/4;j++){
        float4 c4=cr[j], w4=wr[j];
        a0+=c4.x*w4.x; a1+=c4.y*w4.y; a2+=c4.z*w4.z; a3+=c4.w*w4.w;
    }
    float v=(a0+a1)+(a2+a3);
    __nv_bfloat16 h=__float2bfloat16(v);
    __nv_bfloat16 l=__float2bfloat16(v-__bfloat162float(h));
    g_qh[b*KK+k]=*(unsigned short*)&h;
    g_ql[b*KK+k]=*(unsigned short*)&l;
}

// -------- kernel 2: slot hi/lo split
__global__ __launch_bounds__(256)
void k_ksplit(const float* __restrict__ slot){
    int rid = blockIdx.x*256 + threadIdx.x;
    if(rid>=NSLOT) return;
    const float4* src=(const float4*)(slot+(size_t)rid*KK);
    uint2* dh=(uint2*)(g_kh+(size_t)rid*KK);
    uint2* dl=(uint2*)(g_kl+(size_t)rid*KK);
#pragma unroll
    for(int j=0;j<16;j++){
        float4 v=src[j];
        __nv_bfloat162 a,b,c,d;
        a.x=__float2bfloat16(v.x); a.y=__float2bfloat16(v.y);
        b.x=__float2bfloat16(v.z); b.y=__float2bfloat16(v.w);
        c.x=__float2bfloat16(v.x-__bfloat162float(a.x));
        c.y=__float2bfloat16(v.y-__bfloat162float(a.y));
        d.x=__float2bfloat16(v.z-__bfloat162float(b.x));
        d.y=__float2bfloat16(v.w-__bfloat162float(b.y));
        dh[j]=make_uint2(*(unsigned*)&a,*(unsigned*)&b);
        dl[j]=make_uint2(*(unsigned*)&c,*(unsigned*)&d);
    }
}

// -------- kernel 3: R1 scaffolding + MMA-S
// grid 148 = R1 chunking; thread tid = batch row (0..255) for PV/den/partials.
// Warp wid computes S rows [wid*32, wid*32+32) x 64 slots via m16n8k16.
__global__ __launch_bounds__(256,1)
void k_main(const float* __restrict__ slot, const float* __restrict__ prio){
    extern __shared__ __align__(16) char smem[];
    const unsigned sb=(unsigned)__cvta_generic_to_shared(smem);
    const int tid=threadIdx.x, wid=tid>>5, lane=tid&31;
    const int g=lane>>2, tg=lane&3;
    const int c=blockIdx.x;
    const int n0=c*CHUNK, limit=min(n0+CHUNK,NSLOT);
    const int nT=(limit-n0+TN-1)/TN;

    // Q bf16 tiles, all 256 rows, 144B stride
#pragma unroll
    for(int it=0;it<8;it++){
        int idx=tid+it*256, row=idx>>3, pc=idx&7;
        size_t go=(size_t)row*128+(size_t)pc*16;
        cpasync16(sb+QH_OFF+row*144+pc*16,(const char*)g_qh+go,16);
        cpasync16(sb+QL_OFF+row*144+pc*16,(const char*)g_ql+go,16);
    }
    auto tileLoad=[&](int t){
        const int buf=t&1, base=n0+t*TN;
#pragma unroll
        for(int it=0;it<2;it++){
            int idx=tid+it*256, row=idx>>3, pc=idx&7;
            int gn=base+row, ok=(gn<limit)?16:0;
            size_t go=ok?((size_t)gn*128+(size_t)pc*16):0;
            cpasync16(sb+KH_OFF+buf*9216+row*144+pc*16,(const char*)g_kh+go,ok);
            cpasync16(sb+KL_OFF+buf*9216+row*144+pc*16,(const char*)g_kl+go,ok);
        }
#pragma unroll
        for(int it=0;it<4;it++){
            int idx=tid+it*256;
            int gn=base+(idx>>4), ok=(gn<limit)?16:0;
            size_t go=ok?((size_t)gn*256+(size_t)(idx&15)*16):0;
            cpasync16(sb+SF_OFF+buf*16384+idx*16,(const char*)slot+go,ok);
        }
        if(tid<16){
            int gn=base+tid*4, rem=limit-gn;
            int sz=rem>=4?16:(rem>0?rem*4:0);
            cpasync16(sb+PP_OFF+buf*256+tid*16,(const char*)prio+(sz?(size_t)gn*4:0),sz);
        }
        cpcommit();
    };
    tileLoad(0);
    cpwait<0>(); __syncthreads();

    // A fragments (manual loads): rows wid*32+mb*16+{g,g+8}, k-step ks
    unsigned qh[2][4][4], ql[2][4][4];
#pragma unroll
    for(int mb=0;mb<2;mb++)
#pragma unroll
    for(int ks=0;ks<4;ks++){
        unsigned off=(unsigned)((wid*32+mb*16+g)*144+(16*ks+2*tg)*2);
        qh[mb][ks][0]=lds32(sb+QH_OFF+off);
        qh[mb][ks][1]=lds32(sb+QH_OFF+off+8*144);
        qh[mb][ks][2]=lds32(sb+QH_OFF+off+16);
        qh[mb][ks][3]=lds32(sb+QH_OFF+off+8*144+16);
        ql[mb][ks][0]=lds32(sb+QL_OFF+off);
        ql[mb][ks][1]=lds32(sb+QL_OFF+off+8*144);
        ql[mb][ks][2]=lds32(sb+QL_OFF+off+16);
        ql[mb][ks][3]=lds32(sb+QL_OFF+off+8*144+16);
    }

    ull acc2[32];
#pragma unroll
    for(int j=0;j<32;j++) acc2[j]=0ull;
    float den=0.f;
    float* Ps=(float*)(smem+PS_OFF);

    for(int t=0;t<nT;t++){
        const int buf=t&1;
        if(t>0){ cpwait<0>(); __syncthreads(); }
        if(t+1<nT) tileLoad(t+1);

        // ---- S via MMA (3 bf16-split combos), store e = exp(S)*prio
        {
            const unsigned kh=sb+KH_OFF+buf*9216, kl=sb+KL_OFF+buf*9216;
            const float* pp=(const float*)(smem+PP_OFF+buf*256);
#pragma unroll
            for(int mb=0;mb<2;mb++){
                float sc[8][4];
#pragma unroll
                for(int nb=0;nb<8;nb++){sc[nb][0]=sc[nb][1]=sc[nb][2]=sc[nb][3]=0.f;}
#pragma unroll
                for(int ks=0;ks<4;ks++){
#pragma unroll
                    for(int nb=0;nb<8;nb++){
                        unsigned boff=(unsigned)((nb*8+g)*144+(16*ks+2*tg)*2);
                        unsigned b0=lds32(kh+boff), b1=lds32(kh+boff+16);
                        unsigned c0=lds32(kl+boff), c1=lds32(kl+boff+16);
                        mma4(sc[nb],qh[mb][ks],b0,b1);
                        mma4(sc[nb],ql[mb][ks],b0,b1);
                        mma4(sc[nb],qh[mb][ks],c0,c1);
                    }
                }
                int r0=wid*32+mb*16+g, r1=r0+8;
#pragma unroll
                for(int nb=0;nb<8;nb++){
                    int col=nb*8+2*tg;
                    float pa=pp[col], pb=pp[col+1];
                    Ps[r0*PSTR+col]  =__expf(sc[nb][0])*pa;
                    Ps[r0*PSTR+col+1]=__expf(sc[nb][1])*pb;
                    Ps[r1*PSTR+col]  =__expf(sc[nb][2])*pa;
                    Ps[r1*PSTR+col+1]=__expf(sc[nb][3])*pb;
                }
            }
        }
        __syncthreads();

        // ---- PV: R1-exact accumulate; e read from Ps
        {
            const unsigned sf=sb+SF_OFF+buf*16384;
            const float* Pr=Ps+tid*PSTR;
#pragma unroll 2
            for(int i=0;i<TN;i++){
                float e=Pr[i];
                den+=e;
                unsigned eu=__float_as_uint(e);
                ull e2; asm("mov.b64 %0, {%1, %1};":"=l"(e2):"r"(eu));
#pragma unroll
                for(int jj=0;jj<16;jj++){
                    ull a0,a1;
                    lds2(a0,a1,sf+i*256+jj*16);
                    acc2[2*jj]  =ffma2(e2,a0,acc2[2*jj]);
                    acc2[2*jj+1]=ffma2(e2,a1,acc2[2*jj+1]);
                }
            }
        }
        __syncthreads();
    }

    // R1-exact partials
    ull* ap=(ull*)g_accpart + ((size_t)c*BB+tid)*32;
#pragma unroll
    for(int j=0;j<32;j++) ap[j]=acc2[j];
    g_denpart[c*BB+tid]=den;
}

// -------- kernel 4: cross-chunk reduce (proven)
__global__ __launch_bounds__(256)
void k_reduce(){
    int b=blockIdx.x*4+(threadIdx.x>>6);
    int k=threadIdx.x&63;
    float s=0.f, dn=0.f;
#pragma unroll 4
    for(int c=0;c<NCHUNK;c++){
        s +=g_accpart[((size_t)c*BB+b)*KK+k];
        dn+=g_denpart[c*BB+b];
    }
    g_ret[b*KK+k]=s/dn;
}

// -------- kernel 5: decoder (proven)
__global__ __launch_bounds__(256)
void k_dec(const float* __restrict__ wdec, float* __restrict__ out){
    __shared__ float r[4][KK];
    int b0=blockIdx.x*4;
    { int bl=threadIdx.x>>6, k=threadIdx.x&63; r[bl][k]=g_ret[(b0+bl)*KK+k]; }
    __syncthreads();
#pragma unroll
    for(int seg=0;seg<4;seg++){
        int d=threadIdx.x+seg*256;
        const float4* w4=(const float4*)(wdec+(size_t)d*KK);
        float a0=0.f,a1=0.f,a2=0.f,a3=0.f;
#pragma unroll
        for(int j=0;j<16;j++){
            float4 w=w4[j];
            a0+=r[0][4*j]*w.x+r[0][4*j+1]*w.y+r[0][4*j+2]*w.z+r[0][4*j+3]*w.w;
            a1+=r[1][4*j]*w.x+r[1][4*j+1]*w.y+r[1][4*j+2]*w.z+r[1][4*j+3]*w.w;
            a2+=r[2][4*j]*w.x+r[2][4*j+1]*w.y+r[2][4*j+2]*w.z+r[2][4*j+3]*w.w;
            a3+=r[3][4*j]*w.x+r[3][4*j+1]*w.y+r[3][4*j+2]*w.z+r[3][4*j+3]*w.w;
        }
        out[(size_t)(b0+0)*DD+d]=a0;
        out[(size_t)(b0+1)*DD+d]=a1;
        out[(size_t)(b0+2)*DD+d]=a2;
        out[(size_t)(b0+3)*DD+d]=a3;
    }
}

// -------- launch
extern "C" void kernel_launch(void* const* d_in, const int* in_sizes, int n_in,
                              void* d_out, int out_size){
    const float* cue =(const float*)d_in[0];
    const float* slot=(const float*)d_in[1];
    const float* prio=(const float*)d_in[2];
    const float* wcue=(const float*)d_in[3];
    const float* wdec=(const float*)d_in[4];
    float* out=(float*)d_out;

    cudaFuncSetAttribute(k_main, cudaFuncAttributeMaxDynamicSharedMemorySize, SMEM_SZ);
    k_prep<<<64,256>>>(cue,wcue);
    k_ksplit<<<(NSLOT+255)/256,256>>>(slot);
    k_main<<<NCHUNK,256,SMEM_SZ>>>(slot,prio);
    k_reduce<<<64,256>>>();
    k_dec<<<64,256>>>(wdec,out);
}

// round 16
// speedup vs baseline: 1.3372x; 1.3372x over previous
#include <cuda_runtime.h>
#include <cuda_bf16.h>
#include <cstdint>
typedef unsigned long long ull;

#define BB 256
#define DD 1024
#define NSLOT 200000
#define KK 64
#define NCHUNK 148
#define CHUNK ((NSLOT+NCHUNK-1)/NCHUNK)  // 1352
#define TN 64
#define NST 200192                        // 782*256, padded transposed stride

// k_main smem offsets
#define QH_OFF 0u
#define QL_OFF 36864u
#define KH_OFF 73728u     // 2 x 9216
#define KL_OFF 92160u
#define TH_OFF 110592u    // 2 x 9216 (transposed hi)
#define TL_OFF 129024u
#define PP_OFF 147456u    // 2 x 256
#define SMEM_SZ 147968

__device__ __align__(16) unsigned short g_qh[BB*KK];
__device__ __align__(16) unsigned short g_ql[BB*KK];
__device__ __align__(16) unsigned short g_kh[(size_t)NSLOT*KK];
__device__ __align__(16) unsigned short g_kl[(size_t)NSLOT*KK];
__device__ __align__(16) unsigned short g_kht[(size_t)KK*NST];
__device__ __align__(16) unsigned short g_klt[(size_t)KK*NST];
__device__ __align__(16) float g_accpart[NCHUNK*BB*KK];
__device__ __align__(16) float g_denpart[NCHUNK*BB];
__device__ __align__(16) float g_ret[BB*KK];

__device__ __forceinline__ void cpasync16(unsigned d, const void* s, int sz){
    asm volatile("cp.async.cg.shared.global [%0], [%1], 16, %2;"::"r"(d),"l"(s),"r"(sz));
}
__device__ __forceinline__ void cpcommit(){ asm volatile("cp.async.commit_group;"); }
template<int N> __device__ __forceinline__ void cpwait(){
    asm volatile("cp.async.wait_group %0;"::"n"(N));
}
__device__ __forceinline__ unsigned lds32(unsigned a){
    unsigned v; asm volatile("ld.shared.b32 %0, [%1];":"=r"(v):"r"(a)); return v;
}
__device__ __forceinline__ void mma4(float* c, const unsigned* a, unsigned b0, unsigned b1){
    asm volatile("mma.sync.aligned.m16n8k16.row.col.f32.bf16.bf16.f32 "
                 "{%0,%1,%2,%3}, {%4,%5,%6,%7}, {%8,%9}, {%0,%1,%2,%3};"
                 :"+f"(c[0]),"+f"(c[1]),"+f"(c[2]),"+f"(c[3])
                 :"r"(a[0]),"r"(a[1]),"r"(a[2]),"r"(a[3]),"r"(b0),"r"(b1));
}
__device__ __forceinline__ unsigned packbf(float a, float b, float& ra, float& rb){
    __nv_bfloat162 h;
    h.x=__float2bfloat16(a); h.y=__float2bfloat16(b);
    ra=a-__bfloat162float(h.x); rb=b-__bfloat162float(h.y);
    return *(unsigned*)&h;
}
__device__ __forceinline__ unsigned packbf2(float a, float b){
    __nv_bfloat162 h;
    h.x=__float2bfloat16(a); h.y=__float2bfloat16(b);
    return *(unsigned*)&h;
}

// -------- kernel 1: cue projection + Q hi/lo split
__global__ __launch_bounds__(256)
void k_prep(const float* __restrict__ cue, const float* __restrict__ wcue){
    int b = blockIdx.x*4 + (threadIdx.x>>6);
    int k = threadIdx.x & 63;
    const float4* cr=(const float4*)(cue+(size_t)b*DD);
    const float4* wr=(const float4*)(wcue+(size_t)k*DD);
    float a0=0.f,a1=0.f,a2=0.f,a3=0.f;
#pragma unroll 8
    for(int j=0;j<DD/4;j++){
        float4 c4=cr[j], w4=wr[j];
        a0+=c4.x*w4.x; a1+=c4.y*w4.y; a2+=c4.z*w4.z; a3+=c4.w*w4.w;
    }
    float v=(a0+a1)+(a2+a3);
    __nv_bfloat16 h=__float2bfloat16(v);
    __nv_bfloat16 l=__float2bfloat16(v-__bfloat162float(h));
    g_qh[b*KK+k]=*(unsigned short*)&h;
    g_ql[b*KK+k]=*(unsigned short*)&l;
}

// -------- kernel 2: slot hi/lo split + transposed copies
__global__ __launch_bounds__(256)
void k_ksplit(const float* __restrict__ slot){
    extern __shared__ unsigned short sh[];      // shh[256][66], shl[256][66]
    unsigned short* shh=sh;
    unsigned short* shl=sh+256*66;
    const int tid=threadIdx.x;
    const int base=blockIdx.x*256, rid=base+tid;
    const bool ok = rid<NSLOT;
    const float4* src=(const float4*)(slot+(size_t)(ok?rid:0)*KK);
    uint2* dh=(uint2*)(g_kh+(size_t)(ok?rid:0)*KK);
    uint2* dl=(uint2*)(g_kl+(size_t)(ok?rid:0)*KK);
#pragma unroll
    for(int j=0;j<16;j++){
        float4 v = ok ? src[j] : make_float4(0.f,0.f,0.f,0.f);
        __nv_bfloat162 a,b,c,d;
        a.x=__float2bfloat16(v.x); a.y=__float2bfloat16(v.y);
        b.x=__float2bfloat16(v.z); b.y=__float2bfloat16(v.w);
        c.x=__float2bfloat16(v.x-__bfloat162float(a.x));
        c.y=__float2bfloat16(v.y-__bfloat162float(a.y));
        d.x=__float2bfloat16(v.z-__bfloat162float(b.x));
        d.y=__float2bfloat16(v.w-__bfloat162float(b.y));
        if(ok){
            dh[j]=make_uint2(*(unsigned*)&a,*(unsigned*)&b);
            dl[j]=make_uint2(*(unsigned*)&c,*(unsigned*)&d);
        }
        shh[tid*66+4*j  ]=*(unsigned short*)&a.x;
        shh[tid*66+4*j+1]=*(unsigned short*)&a.y;
        shh[tid*66+4*j+2]=*(unsigned short*)&b.x;
        shh[tid*66+4*j+3]=*(unsigned short*)&b.y;
        shl[tid*66+4*j  ]=*(unsigned short*)&c.x;
        shl[tid*66+4*j+1]=*(unsigned short*)&c.y;
        shl[tid*66+4*j+2]=*(unsigned short*)&d.x;
        shl[tid*66+4*j+3]=*(unsigned short*)&d.y;
    }
    __syncthreads();
    const int d=tid>>2, q=tid&3;
#pragma unroll
    for(int i=0;i<8;i++){
        int s0=q*64+i*8;
        unsigned rh[4], rl[4];
#pragma unroll
        for(int w=0;w<4;w++){
            rh[w]=(unsigned)shh[(s0+2*w)*66+d] | ((unsigned)shh[(s0+2*w+1)*66+d]<<16);
            rl[w]=(unsigned)shl[(s0+2*w)*66+d] | ((unsigned)shl[(s0+2*w+1)*66+d]<<16);
        }
        *(uint4*)(g_kht+(size_t)d*NST+base+s0)=make_uint4(rh[0],rh[1],rh[2],rh[3]);
        *(uint4*)(g_klt+(size_t)d*NST+base+s0)=make_uint4(rl[0],rl[1],rl[2],rl[3]);
    }
}

// -------- kernel 3: full-MMA flash-attn on proven scaffolding
__global__ __launch_bounds__(256,1)
void k_main(const float* __restrict__ prio){
    extern __shared__ __align__(16) char smem[];
    const unsigned sb=(unsigned)__cvta_generic_to_shared(smem);
    const int tid=threadIdx.x, wid=tid>>5, lane=tid&31;
    const int g=lane>>2, tg=lane&3;
    const int c=blockIdx.x;
    const int n0=c*CHUNK, limit=min(n0+CHUNK,NSLOT);
    const int nT=(limit-n0+TN-1)/TN;

    // Q tiles (144B stride)
#pragma unroll
    for(int it=0;it<8;it++){
        int idx=tid+it*256, row=idx>>3, pc=idx&7;
        size_t go=(size_t)row*128+(size_t)pc*16;
        cpasync16(sb+QH_OFF+row*144+pc*16,(const char*)g_qh+go,16);
        cpasync16(sb+QL_OFF+row*144+pc*16,(const char*)g_ql+go,16);
    }
    auto tileLoad=[&](int t){
        const int buf=t&1, base=n0+t*TN;
#pragma unroll
        for(int it=0;it<2;it++){
            int idx=tid+it*256, row=idx>>3, pc=idx&7;
            int gn=base+row, ok=(gn<limit)?16:0;
            size_t go=ok?((size_t)gn*128+(size_t)pc*16):0;
            cpasync16(sb+KH_OFF+buf*9216+row*144+pc*16,(const char*)g_kh+go,ok);
            cpasync16(sb+KL_OFF+buf*9216+row*144+pc*16,(const char*)g_kl+go,ok);
        }
#pragma unroll
        for(int it=0;it<2;it++){
            int idx=tid+it*256, d=idx>>3, pc=idx&7;
            size_t go=(size_t)d*NST*2+(size_t)base*2+(size_t)pc*16;
            cpasync16(sb+TH_OFF+buf*9216+d*144+pc*16,(const char*)g_kht+go,16);
            cpasync16(sb+TL_OFF+buf*9216+d*144+pc*16,(const char*)g_klt+go,16);
        }
        if(tid<16){
            int gn=base+tid*4, rem=limit-gn;
            int sz=rem>=4?16:(rem>0?rem*4:0);
            cpasync16(sb+PP_OFF+buf*256+tid*16,(const char*)prio+(sz?(size_t)gn*4:0),sz);
        }
        cpcommit();
    };
    tileLoad(0);

    float o[2][8][4];
#pragma unroll
    for(int mb=0;mb<2;mb++)
#pragma unroll
    for(int nb=0;nb<8;nb++){o[mb][nb][0]=o[mb][nb][1]=o[mb][nb][2]=o[mb][nb][3]=0.f;}
    float den0[2]={0.f,0.f}, den1[2]={0.f,0.f};

    for(int t=0;t<nT;t++){
        const int buf=t&1;
        cpwait<0>(); __syncthreads();
        if(t+1<nT) tileLoad(t+1);

        const unsigned kh=sb+KH_OFF+buf*9216, kl=sb+KL_OFF+buf*9216;
        const unsigned th=sb+TH_OFF+buf*9216, tl=sb+TL_OFF+buf*9216;
        const float* pp=(const float*)(smem+PP_OFF+buf*256);

#pragma unroll
        for(int mb=0;mb<2;mb++){
            // Q A-frags for this mb (proven pattern)
            unsigned qa[4][4], qb[4][4];
#pragma unroll
            for(int ks=0;ks<4;ks++){
                unsigned off=(unsigned)((wid*32+mb*16+g)*144+(16*ks+2*tg)*2);
                qa[ks][0]=lds32(sb+QH_OFF+off);       qa[ks][1]=lds32(sb+QH_OFF+off+8*144);
                qa[ks][2]=lds32(sb+QH_OFF+off+16);    qa[ks][3]=lds32(sb+QH_OFF+off+8*144+16);
                qb[ks][0]=lds32(sb+QL_OFF+off);       qb[ks][1]=lds32(sb+QL_OFF+off+8*144);
                qb[ks][2]=lds32(sb+QL_OFF+off+16);    qb[ks][3]=lds32(sb+QL_OFF+off+8*144+16);
            }
            // S = Q@K^T (proven)
            float sc[8][4];
#pragma unroll
            for(int nb=0;nb<8;nb++){sc[nb][0]=sc[nb][1]=sc[nb][2]=sc[nb][3]=0.f;}
#pragma unroll
            for(int ks=0;ks<4;ks++){
#pragma unroll
                for(int nb=0;nb<8;nb++){
                    unsigned boff=(unsigned)((nb*8+g)*144+(16*ks+2*tg)*2);
                    unsigned b0=lds32(kh+boff), b1=lds32(kh+boff+16);
                    unsigned c0=lds32(kl+boff), c1=lds32(kl+boff+16);
                    mma4(sc[nb],qa[ks],b0,b1);
                    mma4(sc[nb],qb[ks],b0,b1);
                    mma4(sc[nb],qa[ks],c0,c1);
                }
            }
            // per k-step of PV: pack P from C-frags (proven maps), then MMA
#pragma unroll
            for(int ksv=0;ksv<4;ksv++){
                float e[2][4], r[2][4];
#pragma unroll
                for(int hb=0;hb<2;hb++){
                    int nb=2*ksv+hb, col=nb*8+2*tg;
                    float pa=pp[col], pb=pp[col+1];
                    e[hb][0]=__expf(sc[nb][0])*pa;
                    e[hb][1]=__expf(sc[nb][1])*pb;
                    e[hb][2]=__expf(sc[nb][2])*pa;
                    e[hb][3]=__expf(sc[nb][3])*pb;
                    den0[mb]+=e[hb][0]+e[hb][1];
                    den1[mb]+=e[hb][2]+e[hb][3];
                }
                unsigned ah[4], al[4];
                ah[0]=packbf(e[0][0],e[0][1],r[0][0],r[0][1]);
                ah[1]=packbf(e[0][2],e[0][3],r[0][2],r[0][3]);
                ah[2]=packbf(e[1][0],e[1][1],r[1][0],r[1][1]);
                ah[3]=packbf(e[1][2],e[1][3],r[1][2],r[1][3]);
                al[0]=packbf2(r[0][0],r[0][1]);
                al[1]=packbf2(r[0][2],r[0][3]);
                al[2]=packbf2(r[1][0],r[1][1]);
                al[3]=packbf2(r[1][2],r[1][3]);
#pragma unroll
                for(int nd=0;nd<8;nd++){
                    unsigned boff=(unsigned)((nd*8+g)*144+(16*ksv+2*tg)*2);
                    unsigned b0=lds32(th+boff), b1=lds32(th+boff+16);
                    unsigned c0=lds32(tl+boff), c1=lds32(tl+boff+16);
                    mma4(o[mb][nd],ah,b0,b1);
                    mma4(o[mb][nd],al,b0,b1);
                    mma4(o[mb][nd],ah,c0,c1);
                }
            }
        }
        __syncthreads();
    }

    // epilogue: O frags + den to partials
#pragma unroll
    for(int mb=0;mb<2;mb++){
        int r0=wid*32+mb*16+g, r1=r0+8;
#pragma unroll
        for(int nd=0;nd<8;nd++){
            int col=nd*8+2*tg;
            *(float2*)(g_accpart+((size_t)c*BB+r0)*KK+col)=make_float2(o[mb][nd][0],o[mb][nd][1]);
            *(float2*)(g_accpart+((size_t)c*BB+r1)*KK+col)=make_float2(o[mb][nd][2],o[mb][nd][3]);
        }
        float d0=den0[mb], d1=den1[mb];
        d0+=__shfl_xor_sync(0xffffffffu,d0,1); d0+=__shfl_xor_sync(0xffffffffu,d0,2);
        d1+=__shfl_xor_sync(0xffffffffu,d1,1); d1+=__shfl_xor_sync(0xffffffffu,d1,2);
        if(tg==0){
            g_denpart[c*BB+r0]=d0;
            g_denpart[c*BB+r1]=d1;
        }
    }
}

// -------- kernel 4: cross-chunk reduce
__global__ __launch_bounds__(256)
void k_reduce(){
    int b=blockIdx.x*4+(threadIdx.x>>6);
    int k=threadIdx.x&63;
    float s=0.f, dn=0.f;
#pragma unroll 8
    for(int c=0;c<NCHUNK;c++){
        s +=g_accpart[((size_t)c*BB+b)*KK+k];
        dn+=g_denpart[c*BB+b];
    }
    g_ret[b*KK+k]=s/dn;
}

// -------- kernel 5: decoder
__global__ __launch_bounds__(256)
void k_dec(const float* __restrict__ wdec, float* __restrict__ out){
    __shared__ float r[4][KK];
    int b0=blockIdx.x*4;
    { int bl=threadIdx.x>>6, k=threadIdx.x&63; r[bl][k]=g_ret[(b0+bl)*KK+k]; }
    __syncthreads();
#pragma unroll
    for(int seg=0;seg<4;seg++){
        int d=threadIdx.x+seg*256;
        const float4* w4=(const float4*)(wdec+(size_t)d*KK);
        float a0=0.f,a1=0.f,a2=0.f,a3=0.f;
#pragma unroll
        for(int j=0;j<16;j++){
            float4 w=w4[j];
            a0+=r[0][4*j]*w.x+r[0][4*j+1]*w.y+r[0][4*j+2]*w.z+r[0][4*j+3]*w.w;
            a1+=r[1][4*j]*w.x+r[1][4*j+1]*w.y+r[1][4*j+2]*w.z+r[1][4*j+3]*w.w;
            a2+=r[2][4*j]*w.x+r[2][4*j+1]*w.y+r[2][4*j+2]*w.z+r[2][4*j+3]*w.w;
            a3+=r[3][4*j]*w.x+r[3][4*j+1]*w.y+r[3][4*j+2]*w.z+r[3][4*j+3]*w.w;
        }
        out[(size_t)(b0+0)*DD+d]=a0;
        out[(size_t)(b0+1)*DD+d]=a1;
        out[(size_t)(b0+2)*DD+d]=a2;
        out[(size_t)(b0+3)*DD+d]=a3;
    }
}

// -------- launch
extern "C" void kernel_launch(void* const* d_in, const int* in_sizes, int n_in,
                              void* d_out, int out_size){
    const float* cue =(const float*)d_in[0];
    const float* slot=(const float*)d_in[1];
    const float* prio=(const float*)d_in[2];
    const float* wcue=(const float*)d_in[3];
    const float* wdec=(const float*)d_in[4];
    float* out=(float*)d_out;

    cudaFuncSetAttribute(k_ksplit, cudaFuncAttributeMaxDynamicSharedMemorySize, 67584);
    cudaFuncSetAttribute(k_main, cudaFuncAttributeMaxDynamicSharedMemorySize, SMEM_SZ);
    k_prep<<<64,256>>>(cue,wcue);
    k_ksplit<<<(NSLOT+255)/256,256,67584>>>(slot);
    k_main<<<NCHUNK,256,SMEM_SZ>>>(prio);
    k_reduce<<<64,256>>>();
    k_dec<<<64,256>>>(wdec,out);
}

// round 17
// speedup vs baseline: 1.4105x; 1.0548x over previous
#include <cuda_runtime.h>
#include <cuda_bf16.h>
#include <cstdint>
typedef unsigned long long ull;

#define BB 256
#define DD 1024
#define NSLOT 200000
#define KK 64
#define NCHUNK 148
#define CHUNK ((NSLOT+NCHUNK-1)/NCHUNK)  // 1352
#define TN 64
#define NST 200192

#define QH_OFF 0u
#define QL_OFF 36864u
#define KH_OFF 73728u
#define KL_OFF 92160u
#define TH_OFF 110592u
#define TL_OFF 129024u
#define PP_OFF 147456u
#define SMEM_SZ 147968

__device__ __align__(16) unsigned short g_qh[BB*KK];
__device__ __align__(16) unsigned short g_ql[BB*KK];
__device__ __align__(16) unsigned short g_kh[(size_t)NSLOT*KK];
__device__ __align__(16) unsigned short g_kl[(size_t)NSLOT*KK];
__device__ __align__(16) unsigned short g_kht[(size_t)KK*NST];
__device__ __align__(16) unsigned short g_klt[(size_t)KK*NST];
__device__ __align__(16) float g_accpart[NCHUNK*BB*KK];
__device__ __align__(16) float g_denpart[NCHUNK*BB];
__device__ __align__(16) float g_ret[BB*KK];

__device__ __forceinline__ void cpasync16(unsigned d, const void* s, int sz){
    asm volatile("cp.async.cg.shared.global [%0], [%1], 16, %2;"::"r"(d),"l"(s),"r"(sz));
}
__device__ __forceinline__ void cpcommit(){ asm volatile("cp.async.commit_group;"); }
template<int N> __device__ __forceinline__ void cpwait(){
    asm volatile("cp.async.wait_group %0;"::"n"(N));
}
__device__ __forceinline__ unsigned lds32(unsigned a){
    unsigned v; asm volatile("ld.shared.b32 %0, [%1];":"=r"(v):"r"(a)); return v;
}
__device__ __forceinline__ void mma4(float* c, const unsigned* a, unsigned b0, unsigned b1){
    asm volatile("mma.sync.aligned.m16n8k16.row.col.f32.bf16.bf16.f32 "
                 "{%0,%1,%2,%3}, {%4,%5,%6,%7}, {%8,%9}, {%0,%1,%2,%3};"
                 :"+f"(c[0]),"+f"(c[1]),"+f"(c[2]),"+f"(c[3])
                 :"r"(a[0]),"r"(a[1]),"r"(a[2]),"r"(a[3]),"r"(b0),"r"(b1));
}
__device__ __forceinline__ unsigned packbf(float a, float b, float& ra, float& rb){
    __nv_bfloat162 h;
    h.x=__float2bfloat16(a); h.y=__float2bfloat16(b);
    ra=a-__bfloat162float(h.x); rb=b-__bfloat162float(h.y);
    return *(unsigned*)&h;
}
__device__ __forceinline__ unsigned packbf2(float a, float b){
    __nv_bfloat162 h;
    h.x=__float2bfloat16(a); h.y=__float2bfloat16(b);
    return *(unsigned*)&h;
}

// -------- kernel 1: cue projection + Q hi/lo split (proven)
__global__ __launch_bounds__(256)
void k_prep(const float* __restrict__ cue, const float* __restrict__ wcue){
    int b = blockIdx.x*4 + (threadIdx.x>>6);
    int k = threadIdx.x & 63;
    const float4* cr=(const float4*)(cue+(size_t)b*DD);
    const float4* wr=(const float4*)(wcue+(size_t)k*DD);
    float a0=0.f,a1=0.f,a2=0.f,a3=0.f;
#pragma unroll 8
    for(int j=0;j<DD/4;j++){
        float4 c4=cr[j], w4=wr[j];
        a0+=c4.x*w4.x; a1+=c4.y*w4.y; a2+=c4.z*w4.z; a3+=c4.w*w4.w;
    }
    float v=(a0+a1)+(a2+a3);
    __nv_bfloat16 h=__float2bfloat16(v);
    __nv_bfloat16 l=__float2bfloat16(v-__bfloat162float(h));
    g_qh[b*KK+k]=*(unsigned short*)&h;
    g_ql[b*KK+k]=*(unsigned short*)&l;
}

// -------- kernel 2: slot hi/lo split + transposed copies (proven)
__global__ __launch_bounds__(256)
void k_ksplit(const float* __restrict__ slot){
    extern __shared__ unsigned short sh[];
    unsigned short* shh=sh;
    unsigned short* shl=sh+256*66;
    const int tid=threadIdx.x;
    const int base=blockIdx.x*256, rid=base+tid;
    const bool ok = rid<NSLOT;
    const float4* src=(const float4*)(slot+(size_t)(ok?rid:0)*KK);
    uint2* dh=(uint2*)(g_kh+(size_t)(ok?rid:0)*KK);
    uint2* dl=(uint2*)(g_kl+(size_t)(ok?rid:0)*KK);
#pragma unroll
    for(int j=0;j<16;j++){
        float4 v = ok ? src[j] : make_float4(0.f,0.f,0.f,0.f);
        __nv_bfloat162 a,b,c,d;
        a.x=__float2bfloat16(v.x); a.y=__float2bfloat16(v.y);
        b.x=__float2bfloat16(v.z); b.y=__float2bfloat16(v.w);
        c.x=__float2bfloat16(v.x-__bfloat162float(a.x));
        c.y=__float2bfloat16(v.y-__bfloat162float(a.y));
        d.x=__float2bfloat16(v.z-__bfloat162float(b.x));
        d.y=__float2bfloat16(v.w-__bfloat162float(b.y));
        if(ok){
            dh[j]=make_uint2(*(unsigned*)&a,*(unsigned*)&b);
            dl[j]=make_uint2(*(unsigned*)&c,*(unsigned*)&d);
        }
        shh[tid*66+4*j  ]=*(unsigned short*)&a.x;
        shh[tid*66+4*j+1]=*(unsigned short*)&a.y;
        shh[tid*66+4*j+2]=*(unsigned short*)&b.x;
        shh[tid*66+4*j+3]=*(unsigned short*)&b.y;
        shl[tid*66+4*j  ]=*(unsigned short*)&c.x;
        shl[tid*66+4*j+1]=*(unsigned short*)&c.y;
        shl[tid*66+4*j+2]=*(unsigned short*)&d.x;
        shl[tid*66+4*j+3]=*(unsigned short*)&d.y;
    }
    __syncthreads();
    const int d=tid>>2, q=tid&3;
#pragma unroll
    for(int i=0;i<8;i++){
        int s0=q*64+i*8;
        unsigned rh[4], rl[4];
#pragma unroll
        for(int w=0;w<4;w++){
            rh[w]=(unsigned)shh[(s0+2*w)*66+d] | ((unsigned)shh[(s0+2*w+1)*66+d]<<16);
            rl[w]=(unsigned)shl[(s0+2*w)*66+d] | ((unsigned)shl[(s0+2*w+1)*66+d]<<16);
        }
        *(uint4*)(g_kht+(size_t)d*NST+base+s0)=make_uint4(rh[0],rh[1],rh[2],rh[3]);
        *(uint4*)(g_klt+(size_t)d*NST+base+s0)=make_uint4(rl[0],rl[1],rl[2],rl[3]);
    }
}

// -------- kernel 3: full-MMA flash-attn; B-frags hoisted across both M-blocks
__global__ __launch_bounds__(256,1)
void k_main(const float* __restrict__ prio){
    extern __shared__ __align__(16) char smem[];
    const unsigned sb=(unsigned)__cvta_generic_to_shared(smem);
    const int tid=threadIdx.x, wid=tid>>5, lane=tid&31;
    const int g=lane>>2, tg=lane&3;
    const int c=blockIdx.x;
    const int n0=c*CHUNK, limit=min(n0+CHUNK,NSLOT);
    const int nT=(limit-n0+TN-1)/TN;

#pragma unroll
    for(int it=0;it<8;it++){
        int idx=tid+it*256, row=idx>>3, pc=idx&7;
        size_t go=(size_t)row*128+(size_t)pc*16;
        cpasync16(sb+QH_OFF+row*144+pc*16,(const char*)g_qh+go,16);
        cpasync16(sb+QL_OFF+row*144+pc*16,(const char*)g_ql+go,16);
    }
    auto tileLoad=[&](int t){
        const int buf=t&1, base=n0+t*TN;
#pragma unroll
        for(int it=0;it<2;it++){
            int idx=tid+it*256, row=idx>>3, pc=idx&7;
            int gn=base+row, ok=(gn<limit)?16:0;
            size_t go=ok?((size_t)gn*128+(size_t)pc*16):0;
            cpasync16(sb+KH_OFF+buf*9216+row*144+pc*16,(const char*)g_kh+go,ok);
            cpasync16(sb+KL_OFF+buf*9216+row*144+pc*16,(const char*)g_kl+go,ok);
        }
#pragma unroll
        for(int it=0;it<2;it++){
            int idx=tid+it*256, d=idx>>3, pc=idx&7;
            size_t go=(size_t)d*NST*2+(size_t)base*2+(size_t)pc*16;
            cpasync16(sb+TH_OFF+buf*9216+d*144+pc*16,(const char*)g_kht+go,16);
            cpasync16(sb+TL_OFF+buf*9216+d*144+pc*16,(const char*)g_klt+go,16);
        }
        if(tid<16){
            int gn=base+tid*4, rem=limit-gn;
            int sz=rem>=4?16:(rem>0?rem*4:0);
            cpasync16(sb+PP_OFF+buf*256+tid*16,(const char*)prio+(sz?(size_t)gn*4:0),sz);
        }
        cpcommit();
    };
    tileLoad(0);

    float o[2][8][4];
#pragma unroll
    for(int mb=0;mb<2;mb++)
#pragma unroll
    for(int nb=0;nb<8;nb++){o[mb][nb][0]=o[mb][nb][1]=o[mb][nb][2]=o[mb][nb][3]=0.f;}
    float den0[2]={0.f,0.f}, den1[2]={0.f,0.f};

    for(int t=0;t<nT;t++){
        const int buf=t&1;
        cpwait<0>(); __syncthreads();
        if(t+1<nT) tileLoad(t+1);

        const unsigned kh=sb+KH_OFF+buf*9216, kl=sb+KL_OFF+buf*9216;
        const unsigned th=sb+TH_OFF+buf*9216, tl=sb+TL_OFF+buf*9216;
        const float* pp=(const float*)(smem+PP_OFF+buf*256);

        // ---- S phase: ks outer, B loaded once, both mb consume
        float sc[2][8][4];
#pragma unroll
        for(int mb=0;mb<2;mb++)
#pragma unroll
        for(int nb=0;nb<8;nb++){sc[mb][nb][0]=sc[mb][nb][1]=sc[mb][nb][2]=sc[mb][nb][3]=0.f;}
#pragma unroll
        for(int ks=0;ks<4;ks++){
            unsigned qa0[4],qb0[4],qa1[4],qb1[4];
            {
                unsigned off0=(unsigned)((wid*32+g)*144+(16*ks+2*tg)*2);
                qa0[0]=lds32(sb+QH_OFF+off0);       qa0[1]=lds32(sb+QH_OFF+off0+8*144);
                qa0[2]=lds32(sb+QH_OFF+off0+16);    qa0[3]=lds32(sb+QH_OFF+off0+8*144+16);
                qb0[0]=lds32(sb+QL_OFF+off0);       qb0[1]=lds32(sb+QL_OFF+off0+8*144);
                qb0[2]=lds32(sb+QL_OFF+off0+16);    qb0[3]=lds32(sb+QL_OFF+off0+8*144+16);
                unsigned off1=off0+16*144;
                qa1[0]=lds32(sb+QH_OFF+off1);       qa1[1]=lds32(sb+QH_OFF+off1+8*144);
                qa1[2]=lds32(sb+QH_OFF+off1+16);    qa1[3]=lds32(sb+QH_OFF+off1+8*144+16);
                qb1[0]=lds32(sb+QL_OFF+off1);       qb1[1]=lds32(sb+QL_OFF+off1+8*144);
                qb1[2]=lds32(sb+QL_OFF+off1+16);    qb1[3]=lds32(sb+QL_OFF+off1+8*144+16);
            }
#pragma unroll
            for(int nb=0;nb<8;nb++){
                unsigned boff=(unsigned)((nb*8+g)*144+(16*ks+2*tg)*2);
                unsigned b0=lds32(kh+boff), b1=lds32(kh+boff+16);
                unsigned c0=lds32(kl+boff), c1=lds32(kl+boff+16);
                mma4(sc[0][nb],qa0,b0,b1);
                mma4(sc[0][nb],qb0,b0,b1);
                mma4(sc[0][nb],qa0,c0,c1);
                mma4(sc[1][nb],qa1,b0,b1);
                mma4(sc[1][nb],qb1,b0,b1);
                mma4(sc[1][nb],qa1,c0,c1);
            }
        }

        // ---- PV phase: ksv outer, pack both mb, V loaded once
#pragma unroll
        for(int ksv=0;ksv<4;ksv++){
            unsigned ah0[4],al0[4],ah1[4],al1[4];
#pragma unroll
            for(int mb=0;mb<2;mb++){
                float e[2][4], r[2][4];
#pragma unroll
                for(int hb=0;hb<2;hb++){
                    int nb=2*ksv+hb, col=nb*8+2*tg;
                    float pa=pp[col], pb=pp[col+1];
                    e[hb][0]=__expf(sc[mb][nb][0])*pa;
                    e[hb][1]=__expf(sc[mb][nb][1])*pb;
                    e[hb][2]=__expf(sc[mb][nb][2])*pa;
                    e[hb][3]=__expf(sc[mb][nb][3])*pb;
                    den0[mb]+=e[hb][0]+e[hb][1];
                    den1[mb]+=e[hb][2]+e[hb][3];
                }
                unsigned* ah = mb? ah1: ah0;
                unsigned* al = mb? al1: al0;
                ah[0]=packbf(e[0][0],e[0][1],r[0][0],r[0][1]);
                ah[1]=packbf(e[0][2],e[0][3],r[0][2],r[0][3]);
                ah[2]=packbf(e[1][0],e[1][1],r[1][0],r[1][1]);
                ah[3]=packbf(e[1][2],e[1][3],r[1][2],r[1][3]);
                al[0]=packbf2(r[0][0],r[0][1]);
                al[1]=packbf2(r[0][2],r[0][3]);
                al[2]=packbf2(r[1][0],r[1][1]);
                al[3]=packbf2(r[1][2],r[1][3]);
            }
#pragma unroll
            for(int nd=0;nd<8;nd++){
                unsigned boff=(unsigned)((nd*8+g)*144+(16*ksv+2*tg)*2);
                unsigned b0=lds32(th+boff), b1=lds32(th+boff+16);
                unsigned c0=lds32(tl+boff), c1=lds32(tl+boff+16);
                mma4(o[0][nd],ah0,b0,b1);
                mma4(o[0][nd],al0,b0,b1);
                mma4(o[0][nd],ah0,c0,c1);
                mma4(o[1][nd],ah1,b0,b1);
                mma4(o[1][nd],al1,b0,b1);
                mma4(o[1][nd],ah1,c0,c1);
            }
        }
        __syncthreads();
    }

    // epilogue: O frags + den to partials (proven maps)
#pragma unroll
    for(int mb=0;mb<2;mb++){
        int r0=wid*32+mb*16+g, r1=r0+8;
#pragma unroll
        for(int nd=0;nd<8;nd++){
            int col=nd*8+2*tg;
            *(float2*)(g_accpart+((size_t)c*BB+r0)*KK+col)=make_float2(o[mb][nd][0],o[mb][nd][1]);
            *(float2*)(g_accpart+((size_t)c*BB+r1)*KK+col)=make_float2(o[mb][nd][2],o[mb][nd][3]);
        }
        float d0=den0[mb], d1=den1[mb];
        d0+=__shfl_xor_sync(0xffffffffu,d0,1); d0+=__shfl_xor_sync(0xffffffffu,d0,2);
        d1+=__shfl_xor_sync(0xffffffffu,d1,1); d1+=__shfl_xor_sync(0xffffffffu,d1,2);
        if(tg==0){
            g_denpart[c*BB+r0]=d0;
            g_denpart[c*BB+r1]=d1;
        }
    }
}

// -------- kernel 4: cross-chunk reduce (grid 256, 4-way c-split)
__global__ __launch_bounds__(256)
void k_reduce(){
    __shared__ float sacc[4][64];
    __shared__ float sden[4];
    int b=blockIdx.x;
    int k=threadIdx.x&63, grp=threadIdx.x>>6;
    float s=0.f;
#pragma unroll 4
    for(int c=grp;c<NCHUNK;c+=4)
        s+=g_accpart[((size_t)c*BB+b)*KK+k];
    sacc[grp][k]=s;
    if(threadIdx.x<4){
        float dn=0.f;
        for(int c=(int)threadIdx.x;c<NCHUNK;c+=4) dn+=g_denpart[c*BB+b];
        sden[threadIdx.x]=dn;
    }
    __syncthreads();
    if(grp==0){
        float tot=sacc[0][k]+sacc[1][k]+sacc[2][k]+sacc[3][k];
        float dn=sden[0]+sden[1]+sden[2]+sden[3];
        g_ret[b*KK+k]=tot/dn;
    }
}

// -------- kernel 5: decoder (proven)
__global__ __launch_bounds__(256)
void k_dec(const float* __restrict__ wdec, float* __restrict__ out){
    __shared__ float r[4][KK];
    int b0=blockIdx.x*4;
    { int bl=threadIdx.x>>6, k=threadIdx.x&63; r[bl][k]=g_ret[(b0+bl)*KK+k]; }
    __syncthreads();
#pragma unroll
    for(int seg=0;seg<4;seg++){
        int d=threadIdx.x+seg*256;
        const float4* w4=(const float4*)(wdec+(size_t)d*KK);
        float a0=0.f,a1=0.f,a2=0.f,a3=0.f;
#pragma unroll
        for(int j=0;j<16;j++){
            float4 w=w4[j];
            a0+=r[0][4*j]*w.x+r[0][4*j+1]*w.y+r[0][4*j+2]*w.z+r[0][4*j+3]*w.w;
            a1+=r[1][4*j]*w.x+r[1][4*j+1]*w.y+r[1][4*j+2]*w.z+r[1][4*j+3]*w.w;
            a2+=r[2][4*j]*w.x+r[2][4*j+1]*w.y+r[2][4*j+2]*w.z+r[2][4*j+3]*w.w;
            a3+=r[3][4*j]*w.x+r[3][4*j+1]*w.y+r[3][4*j+2]*w.z+r[3][4*j+3]*w.w;
        }
        out[(size_t)(b0+0)*DD+d]=a0;
        out[(size_t)(b0+1)*DD+d]=a1;
        out[(size_t)(b0+2)*DD+d]=a2;
        out[(size_t)(b0+3)*DD+d]=a3;
    }
}

// -------- launch
extern "C" void kernel_launch(void* const* d_in, const int* in_sizes, int n_in,
                              void* d_out, int out_size){
    const float* cue =(const float*)d_in[0];
    const float* slot=(const float*)d_in[1];
    const float* prio=(const float*)d_in[2];
    const float* wcue=(const float*)d_in[3];
    const float* wdec=(const float*)d_in[4];
    float* out=(float*)d_out;

    cudaFuncSetAttribute(k_ksplit, cudaFuncAttributeMaxDynamicSharedMemorySize, 67584);
    cudaFuncSetAttribute(k_main, cudaFuncAttributeMaxDynamicSharedMemorySize, SMEM_SZ);
    k_prep<<<64,256>>>(cue,wcue);
    k_ksplit<<<(NSLOT+255)/256,256,67584>>>(slot);
    k_main<<<NCHUNK,256,SMEM_SZ>>>(prio);
    k_reduce<<<256,256>>>();
    k_dec<<<64,256>>>(wdec,out);
}